// round 6
// baseline (speedup 1.0000x reference)
#include <cuda_runtime.h>
#include <math.h>

// ---------------------------------------------------------------------------
// Problem constants
// ---------------------------------------------------------------------------
#define SEQ    4096
#define DM     1024
#define NHEAD  16
#define DH     64
#define KER    256
#define STRD   16
#define SLICES 240                 // (4096-256)/16
#define ROWS1  (SLICES*KER)        // 61440

// ---------------------------------------------------------------------------
// Device scratch (no allocation allowed — static __device__ arrays)
// ---------------------------------------------------------------------------
__device__ float g_qkv1 [SEQ*3*DM];     //  50 MB: path @ w_in1^T (+b) shared by all windows
__device__ float g_attn1[ROWS1*DM];     // 252 MB: stage-1 attention output
__device__ float g_x2   [ROWS1*DM];     // 252 MB: relu(combined proj)
__device__ float g_q2   [ROWS1*DM];     // 252 MB: hoisted Q projections for the scan
__device__ float g_wc   [DM*DM];        // w_lin @ w_out1   (folded out-proj1 + linear)
__device__ float g_bc   [DM];
__device__ float g_wp   [2*DM*DM];      // W_kv @ w_out2    (folded out-proj2 + KV proj)
__device__ float g_bp   [2*DM];
__device__ float g_kva  [KER*2*DM];     // K|V ping
__device__ float g_kvb  [KER*2*DM];     // K|V pong
__device__ float g_ao   [KER*DM];       // per-step attention output

// ---------------------------------------------------------------------------
// Generic fp32 GEMM:  C[M,N] = A[M,K] @ op(B) (+bias) (+relu)
//   BT=true : B is [N,K] row-major (C = A B^T)  — the nn.Linear convention
//   BT=false: B is [K,N] row-major (C = A B)    — for weight-folding products
// ---------------------------------------------------------------------------
template<int BM,int BN,int BK,int TM,int TN,bool BT,bool RELU,bool BIAS>
__global__ __launch_bounds__((BM/TM)*(BN/TN))
void gemm_kernel(const float* __restrict__ A, const float* __restrict__ B,
                 const float* __restrict__ bias, float* __restrict__ C,
                 int M, int N, int K)
{
    constexpr int THREADS = (BM/TM)*(BN/TN);
    __shared__ float As[BK][BM+4];
    __shared__ float Bs[BK][BN+4];
    const int tid = threadIdx.x;
    const int bm  = blockIdx.y*BM;
    const int bn  = blockIdx.x*BN;
    const int tx  = tid % (BN/TN);
    const int ty  = tid / (BN/TN);

    float acc[TM][TN];
#pragma unroll
    for (int i=0;i<TM;i++)
#pragma unroll
        for (int j=0;j<TN;j++) acc[i][j]=0.f;

    for (int k0=0;k0<K;k0+=BK){
        {   // A tile: BM x BK, float4 along K, stored transposed
            constexpr int NV=(BM*BK)/(THREADS*4);
#pragma unroll
            for (int i=0;i<NV;i++){
                int idx=(tid+i*THREADS)*4;
                int r=idx/BK, c=idx%BK;
                float4 v=*reinterpret_cast<const float4*>(&A[(long long)(bm+r)*K + k0 + c]);
                As[c+0][r]=v.x; As[c+1][r]=v.y; As[c+2][r]=v.z; As[c+3][r]=v.w;
            }
        }
        if (BT){
            constexpr int NV=(BN*BK)/(THREADS*4);
#pragma unroll
            for (int i=0;i<NV;i++){
                int idx=(tid+i*THREADS)*4;
                int r=idx/BK, c=idx%BK;
                float4 v=*reinterpret_cast<const float4*>(&B[(long long)(bn+r)*K + k0 + c]);
                Bs[c+0][r]=v.x; Bs[c+1][r]=v.y; Bs[c+2][r]=v.z; Bs[c+3][r]=v.w;
            }
        } else {
            constexpr int NV=(BN*BK)/(THREADS*4);
#pragma unroll
            for (int i=0;i<NV;i++){
                int idx=(tid+i*THREADS)*4;
                int r=idx/BN, c=idx%BN;
                float4 v=*reinterpret_cast<const float4*>(&B[(long long)(k0+r)*N + bn + c]);
                *reinterpret_cast<float4*>(&Bs[r][c])=v;
            }
        }
        __syncthreads();
#pragma unroll
        for (int kk=0;kk<BK;kk++){
            float ar[TM], br[TN];
#pragma unroll
            for (int i=0;i<TM;i+=4){
                float4 t=*reinterpret_cast<const float4*>(&As[kk][ty*TM+i]);
                ar[i]=t.x; ar[i+1]=t.y; ar[i+2]=t.z; ar[i+3]=t.w;
            }
#pragma unroll
            for (int j=0;j<TN;j+=4){
                float4 t=*reinterpret_cast<const float4*>(&Bs[kk][tx*TN+j]);
                br[j]=t.x; br[j+1]=t.y; br[j+2]=t.z; br[j+3]=t.w;
            }
#pragma unroll
            for (int i=0;i<TM;i++)
#pragma unroll
                for (int j=0;j<TN;j++)
                    acc[i][j] += ar[i]*br[j];
        }
        __syncthreads();
    }
#pragma unroll
    for (int i=0;i<TM;i++){
        long long r = bm + ty*TM + i;
#pragma unroll
        for (int j=0;j<TN;j+=4){
            int cc = bn + tx*TN + j;
            float4 v;
            v.x=acc[i][j]; v.y=acc[i][j+1]; v.z=acc[i][j+2]; v.w=acc[i][j+3];
            if (BIAS){ v.x+=bias[cc]; v.y+=bias[cc+1]; v.z+=bias[cc+2]; v.w+=bias[cc+3]; }
            if (RELU){ v.x=fmaxf(v.x,0.f); v.y=fmaxf(v.y,0.f); v.z=fmaxf(v.z,0.f); v.w=fmaxf(v.w,0.f); }
            *reinterpret_cast<float4*>(&C[r*(long long)N+cc]) = v;
        }
    }
}

// ---------------------------------------------------------------------------
// Folded-bias GEMV:  out[n] = b0[n] + dot(W[n,:], v)   — warp per row
// ---------------------------------------------------------------------------
__global__ void gemv_bias(const float* __restrict__ W, const float* __restrict__ v,
                          const float* __restrict__ b0, float* __restrict__ outv, int K)
{
    int row = blockIdx.x*8 + threadIdx.y;
    float s=0.f;
    for (int j=threadIdx.x;j<K;j+=32) s += W[(long long)row*K+j]*v[j];
#pragma unroll
    for (int o=16;o>0;o>>=1) s += __shfl_xor_sync(0xffffffffu,s,o);
    if (threadIdx.x==0) outv[row]=b0[row]+s;
}

// ---------------------------------------------------------------------------
// Multi-head attention, fixed 256 keys, Dh=64, 16 queries per block.
// Block = 256 threads. grid = (qtile=16, head=16, window).
// Strides parameterize both the windowed stage-1 case (over qkv1 rows) and
// the per-step recurrence case (Q from g_q2, K/V from the kv ping-pong).
// ---------------------------------------------------------------------------
__global__ __launch_bounds__(256)
void attn_kernel(const float* __restrict__ qp, long long q_wstr, int q_rstr,
                 const float* __restrict__ kp, long long k_wstr, int k_rstr,
                 const float* __restrict__ vp, long long v_wstr, int v_rstr,
                 float*       __restrict__ op, long long o_wstr, int o_rstr)
{
    __shared__ float4 KV4[64][17];     // K or V tile (64 keys x 64 floats, padded)
    __shared__ float  S[16][256];      // score / prob matrix for 16 queries

    const int tid = threadIdx.x;
    const int qt = blockIdx.x, h = blockIdx.y, w = blockIdx.z;

    const float* qbase = qp + (long long)w*q_wstr + (long long)(qt*16)*q_rstr + h*DH;
    const float* kbase = kp + (long long)w*k_wstr + h*DH;
    const float* vbase = vp + (long long)w*v_wstr + h*DH;
    float*       obase = op + (long long)w*o_wstr + (long long)(qt*16)*o_rstr + h*DH;

    const int qy = tid>>4;     // 0..15 query
    const int kx = tid&15;     // 0..15 key lane

    // Q row in registers (16 lanes share a row -> L1 broadcast)
    float4 q4[16];
    {
        const float* qrow = qbase + (long long)qy*q_rstr;
#pragma unroll
        for (int i=0;i<16;i++) q4[i]=*reinterpret_cast<const float4*>(qrow + i*4);
    }

    // Phase A: S = (Q K^T) * 1/sqrt(64)
    for (int kt=0;kt<4;kt++){
#pragma unroll
        for (int i=0;i<4;i++){
            int idx=tid+i*256;
            int r=idx>>4, c4=idx&15;
            KV4[r][c4]=*reinterpret_cast<const float4*>(kbase + (long long)(kt*64+r)*k_rstr + c4*4);
        }
        __syncthreads();
#pragma unroll
        for (int kk=0;kk<4;kk++){
            int k=kk*16+kx;
            float dot=0.f;
#pragma unroll
            for (int d=0;d<16;d++){
                float4 kv=KV4[k][d];
                dot += q4[d].x*kv.x + q4[d].y*kv.y + q4[d].z*kv.z + q4[d].w*kv.w;
            }
            S[qy][kt*64+k]=dot*0.125f;
        }
        __syncthreads();
    }

    // Phase B: row softmax (warp per 2 rows, 8 entries per lane)
    {
        int wid=tid>>5, lane=tid&31;
#pragma unroll
        for (int rr=0;rr<2;rr++){
            int r=wid*2+rr;
            float e[8]; float m=-1e30f;
#pragma unroll
            for (int i=0;i<8;i++){ e[i]=S[r][lane+32*i]; m=fmaxf(m,e[i]); }
#pragma unroll
            for (int o=16;o>0;o>>=1) m=fmaxf(m,__shfl_xor_sync(0xffffffffu,m,o));
            float s=0.f;
#pragma unroll
            for (int i=0;i<8;i++){ e[i]=__expf(e[i]-m); s+=e[i]; }
#pragma unroll
            for (int o=16;o>0;o>>=1) s+=__shfl_xor_sync(0xffffffffu,s,o);
            float inv=1.f/s;
#pragma unroll
            for (int i=0;i<8;i++) S[r][lane+32*i]=e[i]*inv;
        }
    }
    __syncthreads();

    // Phase C: O = P V  (thread = (query, 4 output dims))
    {
        const int dl=tid&15, qy2=tid>>4;
        float4 acc=make_float4(0.f,0.f,0.f,0.f);
        for (int kt=0;kt<4;kt++){
#pragma unroll
            for (int i=0;i<4;i++){
                int idx=tid+i*256;
                int r=idx>>4, c4=idx&15;
                KV4[r][c4]=*reinterpret_cast<const float4*>(vbase + (long long)(kt*64+r)*v_rstr + c4*4);
            }
            __syncthreads();
#pragma unroll
            for (int k2=0;k2<64;k2++){
                float p=S[qy2][kt*64+k2];
                float4 v=KV4[k2][dl];
                acc.x+=p*v.x; acc.y+=p*v.y; acc.z+=p*v.z; acc.w+=p*v.w;
            }
            __syncthreads();
        }
        *reinterpret_cast<float4*>(obase + (long long)qy2*o_rstr + dl*4)=acc;
    }
}

// ---------------------------------------------------------------------------
// Orchestration
// ---------------------------------------------------------------------------
extern "C" void kernel_launch(void* const* d_in, const int* in_sizes, int n_in,
                              void* d_out, int out_size)
{
    const float* path   = (const float*)d_in[0];
    const float* w_in1  = (const float*)d_in[1];
    const float* b_in1  = (const float*)d_in[2];
    const float* w_out1 = (const float*)d_in[3];
    const float* b_out1 = (const float*)d_in[4];
    const float* w_lin  = (const float*)d_in[5];
    const float* b_lin  = (const float*)d_in[6];
    const float* w_in2  = (const float*)d_in[7];
    const float* b_in2  = (const float*)d_in[8];
    const float* w_out2 = (const float*)d_in[9];
    const float* b_out2 = (const float*)d_in[10];
    float* out = (float*)d_out;

    float *qkv1,*attn1,*x2,*q2,*wc,*bc,*wp,*bp,*kva,*kvb,*ao;
    cudaGetSymbolAddress((void**)&qkv1 , g_qkv1 );
    cudaGetSymbolAddress((void**)&attn1, g_attn1);
    cudaGetSymbolAddress((void**)&x2   , g_x2   );
    cudaGetSymbolAddress((void**)&q2   , g_q2   );
    cudaGetSymbolAddress((void**)&wc   , g_wc   );
    cudaGetSymbolAddress((void**)&bc   , g_bc   );
    cudaGetSymbolAddress((void**)&wp   , g_wp   );
    cudaGetSymbolAddress((void**)&bp   , g_bp   );
    cudaGetSymbolAddress((void**)&kva  , g_kva  );
    cudaGetSymbolAddress((void**)&kvb  , g_kvb  );
    cudaGetSymbolAddress((void**)&ao   , g_ao   );

    dim3 blk(256);

    // 1. qkv1 = path @ w_in1^T + b_in1        [4096, 3072]  (shared by all windows)
    gemm_kernel<128,128,16,8,8,true ,false,true ><<<dim3(24,32),blk>>>(path, w_in1, b_in1, qkv1, SEQ, 3*DM, DM);

    // 2. wc = w_lin @ w_out1  (fold out-proj1 + linear),  bc = b_lin + w_lin @ b_out1
    gemm_kernel<128,128,16,8,8,false,false,false><<<dim3(8,8)  ,blk>>>(w_lin, w_out1, nullptr, wc, DM, DM, DM);
    gemv_bias<<<DM/8, dim3(32,8)>>>(w_lin, b_out1, b_lin, bc, DM);

    // 3. wp = W_kv @ w_out2 (fold out-proj2 into next-step KV proj), bp likewise
    gemm_kernel<128,128,16,8,8,false,false,false><<<dim3(8,16) ,blk>>>(w_in2 + DM*DM, w_out2, nullptr, wp, 2*DM, DM, DM);
    gemv_bias<<<(2*DM)/8, dim3(32,8)>>>(w_in2 + DM*DM, b_out2, b_in2 + DM, bp, DM);

    // 4. Stage-1 windowed self-attention -> attn1  [61440, 1024]
    attn_kernel<<<dim3(16,NHEAD,SLICES),blk>>>(
        qkv1,        (long long)STRD*3*DM, 3*DM,
        qkv1 + DM,   (long long)STRD*3*DM, 3*DM,
        qkv1 + 2*DM, (long long)STRD*3*DM, 3*DM,
        attn1,       (long long)KER*DM,    DM);

    // 5. x2 = relu(attn1 @ wc^T + bc)         [61440, 1024]
    gemm_kernel<128,128,16,8,8,true ,true ,true ><<<dim3(8,480),blk>>>(attn1, wc, bc, x2, ROWS1, DM, DM);

    // 6. q2 = x2 @ wq2^T + bq2                [61440, 1024]  (hoisted out of the scan)
    gemm_kernel<128,128,16,8,8,true ,false,true ><<<dim3(8,480),blk>>>(x2, w_in2, b_in2, q2, ROWS1, DM, DM);

    // 7. KV_0 = x2[window 0] @ W_kv^T + b_kv  [256, 2048]
    gemm_kernel<64,64,16,4,4,true ,false,true ><<<dim3(32,4),blk>>>(x2, w_in2 + DM*DM, b_in2 + DM, kva, KER, 2*DM, DM);

    // 8. Sequential recurrence: 239 steps of (attention, folded KV GEMM)
    float* kvp[2] = {kva, kvb};
    int cur = 0;
    for (int t=1; t<SLICES; t++){
        attn_kernel<<<dim3(16,NHEAD,1),blk>>>(
            q2 + (long long)t*KER*DM, 0, DM,
            kvp[cur],                 0, 2*DM,
            kvp[cur] + DM,            0, 2*DM,
            ao,                       0, DM);
        if (t < SLICES-1){
            gemm_kernel<64,64,16,4,4,true,false,true><<<dim3(32,4),blk>>>(ao, wp, bp, kvp[1-cur], KER, 2*DM, DM);
            cur ^= 1;
        } else {
            // final step: real output projection, once
            gemm_kernel<64,64,16,4,4,true,false,true><<<dim3(16,4),blk>>>(ao, w_out2, b_out2, out, KER, DM, DM);
        }
    }
}

// round 10
// speedup vs baseline: 1.9592x; 1.9592x over previous
#include <cuda_runtime.h>
#include <math.h>

// ---------------------------------------------------------------------------
// Problem constants
// ---------------------------------------------------------------------------
#define SEQ    4096
#define DM     1024
#define NHEAD  16
#define DH     64
#define KER    256
#define STRD   16
#define SLICES 240                 // (4096-256)/16
#define ROWS1  (SLICES*KER)        // 61440

// ---------------------------------------------------------------------------
// Device scratch (no allocation allowed — static __device__ arrays)
// ---------------------------------------------------------------------------
__device__ float g_qkv1 [SEQ*3*DM];     // path @ w_in1^T (+b), shared by all windows
__device__ float g_attn1[ROWS1*DM];     // stage-1 attention output
__device__ float g_x2   [ROWS1*DM];     // relu(combined proj)
__device__ float g_q2   [ROWS1*DM];     // hoisted Q projections for the scan
__device__ float g_wc   [DM*DM];        // w_lin @ w_out1   (folded out-proj1 + linear)
__device__ float g_bc   [DM];
__device__ float g_wp   [2*DM*DM];      // W_kv @ w_out2    (folded out-proj2 + KV proj)
__device__ float g_bp   [2*DM];
__device__ float g_kva  [KER*2*DM];     // K|V ping
__device__ float g_kvb  [KER*2*DM];     // K|V pong
__device__ float g_ao   [KER*DM];       // per-step attention output

// ---------------------------------------------------------------------------
// tf32 helpers
// ---------------------------------------------------------------------------
__device__ __forceinline__ unsigned f2tf32(float f){
    unsigned u; asm("cvt.rna.tf32.f32 %0, %1;" : "=r"(u) : "f"(f)); return u;
}
__device__ __forceinline__ void mma_tf32(float* d, const unsigned* a, const unsigned* b){
    asm volatile("mma.sync.aligned.m16n8k8.row.col.f32.tf32.tf32.f32 "
        "{%0,%1,%2,%3}, {%4,%5,%6,%7}, {%8,%9}, {%0,%1,%2,%3};"
        : "+f"(d[0]),"+f"(d[1]),"+f"(d[2]),"+f"(d[3])
        : "r"(a[0]),"r"(a[1]),"r"(a[2]),"r"(a[3]), "r"(b[0]),"r"(b[1]));
}

// ---------------------------------------------------------------------------
// tf32 tensor-core GEMM:  C[M,N] = A[M,K] @ B^T (+bias)(+relu)
// A row-major [M,K], B row-major [N,K] (nn.Linear weight convention).
// 256 threads, BK=16, warp grid (BM/WM) x (BN/WN) = 8 warps.
// Smem tiles [rows][BK+4] -> conflict-free fragment loads (stride 20).
// ---------------------------------------------------------------------------
template<int BM,int BN,int WM,int WN,bool RELU,bool BIAS>
__global__ __launch_bounds__(256)
void gemm_tf32(const float* __restrict__ A, const float* __restrict__ B,
               const float* __restrict__ bias, float* __restrict__ C,
               int M, int N, int K)
{
    constexpr int BK  = 16;
    constexpr int LDS_ = BK + 4;            // 20: conflict-free frag reads
    constexpr int WGN = BN / WN;            // warps along N
    constexpr int MI  = WM / 16, NI = WN / 8;
    __shared__ unsigned As[BM][LDS_];
    __shared__ unsigned Bs[BN][LDS_];

    const int tid = threadIdx.x, wid = tid >> 5, lane = tid & 31;
    const int g = lane >> 2, t4 = lane & 3;
    const int wm = wid / WGN, wn = wid % WGN;
    const int bm = blockIdx.y * BM, bn = blockIdx.x * BN;

    float acc[MI][NI][4] = {};

    for (int k0 = 0; k0 < K; k0 += BK){
        constexpr int AV = (BM*BK)/(256*4);
#pragma unroll
        for (int i=0;i<AV;i++){
            int idx = tid + i*256;
            int r = idx >> 2, c = (idx & 3) * 4;
            float4 v = *reinterpret_cast<const float4*>(&A[(long long)(bm+r)*K + k0 + c]);
            As[r][c+0]=f2tf32(v.x); As[r][c+1]=f2tf32(v.y);
            As[r][c+2]=f2tf32(v.z); As[r][c+3]=f2tf32(v.w);
        }
        constexpr int BV = (BN*BK)/(256*4);
#pragma unroll
        for (int i=0;i<BV;i++){
            int idx = tid + i*256;
            int r = idx >> 2, c = (idx & 3) * 4;
            float4 v = *reinterpret_cast<const float4*>(&B[(long long)(bn+r)*K + k0 + c]);
            Bs[r][c+0]=f2tf32(v.x); Bs[r][c+1]=f2tf32(v.y);
            Bs[r][c+2]=f2tf32(v.z); Bs[r][c+3]=f2tf32(v.w);
        }
        __syncthreads();
#pragma unroll
        for (int k8=0;k8<BK;k8+=8){
            unsigned af[MI][4], bf[NI][2];
#pragma unroll
            for (int mi=0;mi<MI;mi++){
                int rb = wm*WM + mi*16;
                af[mi][0]=As[rb+g  ][k8+t4];
                af[mi][1]=As[rb+g+8][k8+t4];
                af[mi][2]=As[rb+g  ][k8+t4+4];
                af[mi][3]=As[rb+g+8][k8+t4+4];
            }
#pragma unroll
            for (int ni=0;ni<NI;ni++){
                int cb = wn*WN + ni*8;
                bf[ni][0]=Bs[cb+g][k8+t4];
                bf[ni][1]=Bs[cb+g][k8+t4+4];
            }
#pragma unroll
            for (int mi=0;mi<MI;mi++)
#pragma unroll
                for (int ni=0;ni<NI;ni++)
                    mma_tf32(acc[mi][ni], af[mi], bf[ni]);
        }
        __syncthreads();
    }
    // epilogue
#pragma unroll
    for (int mi=0;mi<MI;mi++){
#pragma unroll
        for (int ni=0;ni<NI;ni++){
            int col  = bn + wn*WN + ni*8 + t4*2;
            int row0 = bm + wm*WM + mi*16 + g;
            float b0=0.f, b1=0.f;
            if (BIAS){ b0 = bias[col]; b1 = bias[col+1]; }
            float2 v0 = make_float2(acc[mi][ni][0]+b0, acc[mi][ni][1]+b1);
            float2 v1 = make_float2(acc[mi][ni][2]+b0, acc[mi][ni][3]+b1);
            if (RELU){
                v0.x=fmaxf(v0.x,0.f); v0.y=fmaxf(v0.y,0.f);
                v1.x=fmaxf(v1.x,0.f); v1.y=fmaxf(v1.y,0.f);
            }
            *reinterpret_cast<float2*>(&C[(long long)row0*N + col])     = v0;
            *reinterpret_cast<float2*>(&C[(long long)(row0+8)*N + col]) = v1;
        }
    }
}

// ---------------------------------------------------------------------------
// fp32 scalar GEMM (weight folds only): C[M,N] = A[M,K] @ B[K,N]
// Kept fp32 for accuracy of the folded weights that feed the recurrence.
// ---------------------------------------------------------------------------
template<int BM,int BN,int BK,int TM,int TN>
__global__ __launch_bounds__((BM/TM)*(BN/TN))
void gemm_f32(const float* __restrict__ A, const float* __restrict__ B,
              float* __restrict__ C, int M, int N, int K)
{
    constexpr int THREADS = (BM/TM)*(BN/TN);
    __shared__ float As[BK][BM+4];
    __shared__ float Bs[BK][BN+4];
    const int tid = threadIdx.x;
    const int bm  = blockIdx.y*BM, bn = blockIdx.x*BN;
    const int tx  = tid % (BN/TN), ty = tid / (BN/TN);

    float acc[TM][TN];
#pragma unroll
    for (int i=0;i<TM;i++)
#pragma unroll
        for (int j=0;j<TN;j++) acc[i][j]=0.f;

    for (int k0=0;k0<K;k0+=BK){
        {
            constexpr int NV=(BM*BK)/(THREADS*4);
#pragma unroll
            for (int i=0;i<NV;i++){
                int idx=(tid+i*THREADS)*4;
                int r=idx/BK, c=idx%BK;
                float4 v=*reinterpret_cast<const float4*>(&A[(long long)(bm+r)*K + k0 + c]);
                As[c+0][r]=v.x; As[c+1][r]=v.y; As[c+2][r]=v.z; As[c+3][r]=v.w;
            }
        }
        {
            constexpr int NV=(BN*BK)/(THREADS*4);
#pragma unroll
            for (int i=0;i<NV;i++){
                int idx=(tid+i*THREADS)*4;
                int r=idx/BN, c=idx%BN;
                float4 v=*reinterpret_cast<const float4*>(&B[(long long)(k0+r)*N + bn + c]);
                *reinterpret_cast<float4*>(&Bs[r][c])=v;
            }
        }
        __syncthreads();
#pragma unroll
        for (int kk=0;kk<BK;kk++){
            float ar[TM], br[TN];
#pragma unroll
            for (int i=0;i<TM;i+=4){
                float4 t=*reinterpret_cast<const float4*>(&As[kk][ty*TM+i]);
                ar[i]=t.x; ar[i+1]=t.y; ar[i+2]=t.z; ar[i+3]=t.w;
            }
#pragma unroll
            for (int j=0;j<TN;j+=4){
                float4 t=*reinterpret_cast<const float4*>(&Bs[kk][tx*TN+j]);
                br[j]=t.x; br[j+1]=t.y; br[j+2]=t.z; br[j+3]=t.w;
            }
#pragma unroll
            for (int i=0;i<TM;i++)
#pragma unroll
                for (int j=0;j<TN;j++)
                    acc[i][j] += ar[i]*br[j];
        }
        __syncthreads();
    }
#pragma unroll
    for (int i=0;i<TM;i++){
        long long r = bm + ty*TM + i;
#pragma unroll
        for (int j=0;j<TN;j+=4){
            int cc = bn + tx*TN + j;
            float4 v;
            v.x=acc[i][j]; v.y=acc[i][j+1]; v.z=acc[i][j+2]; v.w=acc[i][j+3];
            *reinterpret_cast<float4*>(&C[r*(long long)N+cc]) = v;
        }
    }
}

// ---------------------------------------------------------------------------
// Folded-bias GEMV:  out[n] = b0[n] + dot(W[n,:], v)   — warp per row
// ---------------------------------------------------------------------------
__global__ void gemv_bias(const float* __restrict__ W, const float* __restrict__ v,
                          const float* __restrict__ b0, float* __restrict__ outv, int K)
{
    int row = blockIdx.x*8 + threadIdx.y;
    float s=0.f;
    for (int j=threadIdx.x;j<K;j+=32) s += W[(long long)row*K+j]*v[j];
#pragma unroll
    for (int o=16;o>0;o>>=1) s += __shfl_xor_sync(0xffffffffu,s,o);
    if (threadIdx.x==0) outv[row]=b0[row]+s;
}

// ---------------------------------------------------------------------------
// tf32 multi-head attention: 32 queries x 256 keys, Dh=64 per block.
// 256 threads (8 warps). grid = (KER/32=8, NHEAD, windows).
// QK^T: warps tile (2 M16) x (4 N32) over 128-key chunks.
// P.V : warps split N=64 (one n8 frag each) -> register accumulators, no reduce.
// Dynamic smem: Q[32][68] | KV[128][68] | S[32][264]  = 77312 bytes.
// ---------------------------------------------------------------------------
#define ATTN_SMEM ((32*68 + 128*68)*4 + 32*264*4)

__global__ __launch_bounds__(256)
void attn_tf32(const float* __restrict__ qp, long long q_wstr, int q_rstr,
               const float* __restrict__ kp, long long k_wstr, int k_rstr,
               const float* __restrict__ vp, long long v_wstr, int v_rstr,
               float*       __restrict__ op, long long o_wstr, int o_rstr)
{
    extern __shared__ unsigned char smraw[];
    unsigned* Qs  = reinterpret_cast<unsigned*>(smraw);   // [32][68]
    unsigned* KVs = Qs + 32*68;                           // [128][68]
    float*    Ss  = reinterpret_cast<float*>(KVs + 128*68); // [32][264]
    unsigned* Ps  = reinterpret_cast<unsigned*>(Ss);

    const int tid = threadIdx.x, wid = tid>>5, lane = tid&31;
    const int g = lane>>2, t4 = lane&3;
    const int qt = blockIdx.x, h = blockIdx.y, w = blockIdx.z;

    const float* qb = qp + (long long)w*q_wstr + (long long)(qt*32)*q_rstr + h*DH;
    const float* kb = kp + (long long)w*k_wstr + h*DH;
    const float* vb = vp + (long long)w*v_wstr + h*DH;
    float*       ob = op + (long long)w*o_wstr + (long long)(qt*32)*o_rstr + h*DH;

    // ---- load Q tile (32 x 64) as tf32
#pragma unroll
    for (int i=0;i<2;i++){
        int idx = tid + i*256, r = idx>>4, c = (idx&15)*4;
        float4 v = *reinterpret_cast<const float4*>(qb + (long long)r*q_rstr + c);
        Qs[r*68+c]=f2tf32(v.x); Qs[r*68+c+1]=f2tf32(v.y);
        Qs[r*68+c+2]=f2tf32(v.z); Qs[r*68+c+3]=f2tf32(v.w);
    }

    // ---- phase A: S = (Q K^T) / 8, over two 128-key chunks
    const int wm = wid & 1, wn = wid >> 1;
    for (int kc=0;kc<2;kc++){
#pragma unroll
        for (int i=0;i<8;i++){
            int idx = tid + i*256, r = idx>>4, c = (idx&15)*4;
            float4 v = *reinterpret_cast<const float4*>(kb + (long long)(kc*128+r)*k_rstr + c);
            KVs[r*68+c]=f2tf32(v.x); KVs[r*68+c+1]=f2tf32(v.y);
            KVs[r*68+c+2]=f2tf32(v.z); KVs[r*68+c+3]=f2tf32(v.w);
        }
        __syncthreads();
        float sacc[4][4] = {};
#pragma unroll
        for (int k8=0;k8<64;k8+=8){
            unsigned af[4];
            const int rb = wm*16;
            af[0]=Qs[(rb+g  )*68 + k8+t4];
            af[1]=Qs[(rb+g+8)*68 + k8+t4];
            af[2]=Qs[(rb+g  )*68 + k8+t4+4];
            af[3]=Qs[(rb+g+8)*68 + k8+t4+4];
#pragma unroll
            for (int ni=0;ni<4;ni++){
                int nb = wn*32 + ni*8;
                unsigned bf[2];
                bf[0]=KVs[(nb+g)*68 + k8+t4];
                bf[1]=KVs[(nb+g)*68 + k8+t4+4];
                mma_tf32(sacc[ni], af, bf);
            }
        }
#pragma unroll
        for (int ni=0;ni<4;ni++){
            int col = kc*128 + wn*32 + ni*8 + t4*2;
            int row = wm*16 + g;
            *reinterpret_cast<float2*>(&Ss[row*264+col])     = make_float2(sacc[ni][0]*0.125f, sacc[ni][1]*0.125f);
            *reinterpret_cast<float2*>(&Ss[(row+8)*264+col]) = make_float2(sacc[ni][2]*0.125f, sacc[ni][3]*0.125f);
        }
        __syncthreads();
    }

    // ---- phase B: row softmax (warp per 4 rows), write back probs as tf32
#pragma unroll
    for (int rr=0;rr<4;rr++){
        int r = wid*4 + rr;
        float e[8], m=-1e30f;
#pragma unroll
        for (int i=0;i<8;i++){ e[i]=Ss[r*264 + lane + 32*i]; m=fmaxf(m,e[i]); }
#pragma unroll
        for (int o=16;o>0;o>>=1) m=fmaxf(m,__shfl_xor_sync(0xffffffffu,m,o));
        float s=0.f;
#pragma unroll
        for (int i=0;i<8;i++){ e[i]=__expf(e[i]-m); s+=e[i]; }
#pragma unroll
        for (int o=16;o>0;o>>=1) s+=__shfl_xor_sync(0xffffffffu,s,o);
        float inv=1.f/s;
#pragma unroll
        for (int i=0;i<8;i++) Ps[r*264 + lane + 32*i] = f2tf32(e[i]*inv);
    }
    __syncthreads();

    // ---- phase C: O = P V ; warp wid owns output cols [wid*8, wid*8+8)
    float oacc[2][4] = {};
    for (int vc=0;vc<2;vc++){
#pragma unroll
        for (int i=0;i<8;i++){
            int idx = tid + i*256, r = idx>>4, c = (idx&15)*4;
            float4 v = *reinterpret_cast<const float4*>(vb + (long long)(vc*128+r)*v_rstr + c);
            KVs[r*68+c]=f2tf32(v.x); KVs[r*68+c+1]=f2tf32(v.y);
            KVs[r*68+c+2]=f2tf32(v.z); KVs[r*68+c+3]=f2tf32(v.w);
        }
        __syncthreads();
#pragma unroll
        for (int ks=0;ks<16;ks++){
            int kof = vc*128 + ks*8;
            unsigned bf[2];
            bf[0]=KVs[(ks*8+t4  )*68 + wid*8+g];
            bf[1]=KVs[(ks*8+t4+4)*68 + wid*8+g];
#pragma unroll
            for (int mi=0;mi<2;mi++){
                unsigned af[4];
                const int rb = mi*16;
                af[0]=Ps[(rb+g  )*264 + kof+t4];
                af[1]=Ps[(rb+g+8)*264 + kof+t4];
                af[2]=Ps[(rb+g  )*264 + kof+t4+4];
                af[3]=Ps[(rb+g+8)*264 + kof+t4+4];
                mma_tf32(oacc[mi], af, bf);
            }
        }
        __syncthreads();
    }
#pragma unroll
    for (int mi=0;mi<2;mi++){
        int row = mi*16 + g, col = wid*8 + t4*2;
        *reinterpret_cast<float2*>(ob + (long long)row*o_rstr + col)     = make_float2(oacc[mi][0], oacc[mi][1]);
        *reinterpret_cast<float2*>(ob + (long long)(row+8)*o_rstr + col) = make_float2(oacc[mi][2], oacc[mi][3]);
    }
}

// ---------------------------------------------------------------------------
// Orchestration
// ---------------------------------------------------------------------------
extern "C" void kernel_launch(void* const* d_in, const int* in_sizes, int n_in,
                              void* d_out, int out_size)
{
    const float* path   = (const float*)d_in[0];
    const float* w_in1  = (const float*)d_in[1];
    const float* b_in1  = (const float*)d_in[2];
    const float* w_out1 = (const float*)d_in[3];
    const float* b_out1 = (const float*)d_in[4];
    const float* w_lin  = (const float*)d_in[5];
    const float* b_lin  = (const float*)d_in[6];
    const float* w_in2  = (const float*)d_in[7];
    const float* b_in2  = (const float*)d_in[8];
    const float* w_out2 = (const float*)d_in[9];
    const float* b_out2 = (const float*)d_in[10];
    float* out = (float*)d_out;

    float *qkv1,*attn1,*x2,*q2,*wc,*bc,*wp,*bp,*kva,*kvb,*ao;
    cudaGetSymbolAddress((void**)&qkv1 , g_qkv1 );
    cudaGetSymbolAddress((void**)&attn1, g_attn1);
    cudaGetSymbolAddress((void**)&x2   , g_x2   );
    cudaGetSymbolAddress((void**)&q2   , g_q2   );
    cudaGetSymbolAddress((void**)&wc   , g_wc   );
    cudaGetSymbolAddress((void**)&bc   , g_bc   );
    cudaGetSymbolAddress((void**)&wp   , g_wp   );
    cudaGetSymbolAddress((void**)&bp   , g_bp   );
    cudaGetSymbolAddress((void**)&kva  , g_kva  );
    cudaGetSymbolAddress((void**)&kvb  , g_kvb  );
    cudaGetSymbolAddress((void**)&ao   , g_ao   );

    cudaFuncSetAttribute(attn_tf32, cudaFuncAttributeMaxDynamicSharedMemorySize, ATTN_SMEM);

    dim3 blk(256);

    // 1. qkv1 = path @ w_in1^T + b_in1        [4096, 3072]
    gemm_tf32<128,128,32,64,false,true><<<dim3(24,32),blk>>>(path, w_in1, b_in1, qkv1, SEQ, 3*DM, DM);

    // 2. wc = w_lin @ w_out1 (fp32 fold),  bc = b_lin + w_lin @ b_out1
    gemm_f32<128,128,16,8,8><<<dim3(8,8),blk>>>(w_lin, w_out1, wc, DM, DM, DM);
    gemv_bias<<<DM/8, dim3(32,8)>>>(w_lin, b_out1, b_lin, bc, DM);

    // 3. wp = W_kv @ w_out2 (fp32 fold), bp likewise
    gemm_f32<128,128,16,8,8><<<dim3(8,16),blk>>>(w_in2 + DM*DM, w_out2, wp, 2*DM, DM, DM);
    gemv_bias<<<(2*DM)/8, dim3(32,8)>>>(w_in2 + DM*DM, b_out2, b_in2 + DM, bp, DM);

    // 4. Stage-1 windowed self-attention -> attn1  [61440, 1024]
    attn_tf32<<<dim3(8,NHEAD,SLICES),blk,ATTN_SMEM>>>(
        qkv1,        (long long)STRD*3*DM, 3*DM,
        qkv1 + DM,   (long long)STRD*3*DM, 3*DM,
        qkv1 + 2*DM, (long long)STRD*3*DM, 3*DM,
        attn1,       (long long)KER*DM,    DM);

    // 5. x2 = relu(attn1 @ wc^T + bc)         [61440, 1024]
    gemm_tf32<128,128,32,64,true ,true><<<dim3(8,480),blk>>>(attn1, wc, bc, x2, ROWS1, DM, DM);

    // 6. q2 = x2 @ wq2^T + bq2                [61440, 1024]
    gemm_tf32<128,128,32,64,false,true><<<dim3(8,480),blk>>>(x2, w_in2, b_in2, q2, ROWS1, DM, DM);

    // 7. KV_0 = x2[window 0] @ W_kv^T + b_kv  [256, 2048]
    gemm_tf32<64,64,32,16,false,true><<<dim3(32,4),blk>>>(x2, w_in2 + DM*DM, b_in2 + DM, kva, KER, 2*DM, DM);

    // 8. Sequential recurrence: 239 steps of (attention, folded KV GEMM)
    float* kvp[2] = {kva, kvb};
    int cur = 0;
    for (int t=1; t<SLICES; t++){
        attn_tf32<<<dim3(8,NHEAD,1),blk,ATTN_SMEM>>>(
            q2 + (long long)t*KER*DM, 0, DM,
            kvp[cur],                 0, 2*DM,
            kvp[cur] + DM,            0, 2*DM,
            ao,                       0, DM);
        if (t < SLICES-1){
            gemm_tf32<64,64,32,16,false,true><<<dim3(32,4),blk>>>(ao, wp, bp, kvp[1-cur], KER, 2*DM, DM);
            cur ^= 1;
        } else {
            // final step: real output projection, once
            gemm_tf32<64,64,32,16,false,true><<<dim3(16,4),blk>>>(ao, w_out2, b_out2, out, KER, DM, DM);
        }
    }
}